// round 10
// baseline (speedup 1.0000x reference)
#include <cuda_runtime.h>
#include <cuda_fp16.h>
#include <math_constants.h>

// Problem-shape constants (fixed by setup_inputs)
#define NN   50000
#define EN   400000
#define EEN  800000
#define CN   800000

#define FULLMASK 0xffffffffu

// ---------------- static scratch (no allocation allowed) ----------------
__device__ __half  g_qh[(size_t)EN * 128];    // [E,128] q projection (fp16 storage)
__device__ __half  g_kh[(size_t)EN * 128];    // [E,128] k projection (fp16 storage)
__device__ float4 g_vsum[EN];                 // [E,4]  per-head summed v
__device__ float2 g_sn[(size_t)EN * 4];       // [E,4] interleaved (exp-sum, exp*vsum)
__device__ float4 g_S3[NN];                   // stage3 per-head exp-sum
__device__ float  g_whk[4];
__device__ float  g_wv[4];
// folded projection weights (computed by k_prep_all, fp32 exact)
__device__ float  g_W2q[32 * 128];            // W2 @ Wq   [32,128]
__device__ float  g_W2k[32 * 128];            // W2 @ Wk   [32,128]
__device__ float  g_bq[128];                  // b2 @ Wq
__device__ float  g_bk[128];                  // b2 @ Wk
__device__ float4 g_W2v[32];                  // W2 @ wvh  [32,4]
__device__ float4 g_bv;                       // b2 @ wvh

__device__ __forceinline__ unsigned int f2tf32(float f) {
    unsigned int r;
    asm("cvt.rna.tf32.f32 %0, %1;" : "=r"(r) : "f"(f));
    return r;
}

// ---------------- K_prep_all: weight folding + S3 zero-init ----------------
__global__ void k_prep_all(const float* __restrict__ W2, const float* __restrict__ b2,
                           const float* __restrict__ Wq, const float* __restrict__ Wk,
                           const float* __restrict__ Wv,
                           const float* __restrict__ Wq2,
                           const float* __restrict__ Wk2,
                           const float* __restrict__ Wv2, int N) {
    int idx = blockIdx.x * 256 + threadIdx.x;
    if (idx < 4096) {                       // W2q
        int r = idx >> 7, c = idx & 127;
        float s = 0.f;
        for (int m = 0; m < 128; m++) s += W2[r * 128 + m] * Wq[m * 128 + c];
        g_W2q[idx] = s;
    } else if (idx < 8192) {                // W2k
        int i = idx - 4096;
        int r = i >> 7, c = i & 127;
        float s = 0.f;
        for (int m = 0; m < 128; m++) s += W2[r * 128 + m] * Wk[m * 128 + c];
        g_W2k[i] = s;
    } else if (idx < 8320) {                // bq
        int c = idx - 8192;
        float s = 0.f;
        for (int m = 0; m < 128; m++) s += b2[m] * Wq[m * 128 + c];
        g_bq[c] = s;
    } else if (idx < 8448) {                // bk
        int c = idx - 8320;
        float s = 0.f;
        for (int m = 0; m < 128; m++) s += b2[m] * Wk[m * 128 + c];
        g_bk[c] = s;
    } else if (idx < 8576) {                // W2v [32][4] (wvh recomputed inline)
        int i = idx - 8448;
        int r = i >> 2, hh = i & 3;
        float s = 0.f;
        for (int m = 0; m < 128; m++) {
            float w = 0.f;
            for (int d = 0; d < 32; d++) w += Wv[m * 128 + hh * 32 + d];
            s += W2[r * 128 + m] * w;
        }
        ((float*)&g_W2v[r])[hh] = s;
    } else if (idx < 8580) {                // bv
        int hh = idx - 8576;
        float s = 0.f;
        for (int m = 0; m < 128; m++) {
            float w = 0.f;
            for (int d = 0; d < 32; d++) w += Wv[m * 128 + hh * 32 + d];
            s += b2[m] * w;
        }
        ((float*)&g_bv)[hh] = s;
    } else if (idx < 8584) {                // whk
        int h = idx - 8580;
        float qk = 0.f;
        for (int d = 0; d < 32; d++) qk += Wq2[h * 32 + d] * Wk2[h * 32 + d];
        g_whk[h] = qk * 0.17677669529663687f;   // 1/sqrt(32)
    } else if (idx < 8588) {                // wv
        int h = idx - 8584;
        float vv = 0.f;
        for (int d = 0; d < 32; d++) vv += Wv2[h * 32 + d];
        g_wv[h] = vv;
    } else {                                // zero g_S3 (consumed by k_edge atomics)
        int j = idx - 8704;
        if (j >= 0 && j < N)
            g_S3[j] = make_float4(0.f, 0.f, 0.f, 0.f);
    }
}

// ---------------- K1: edge MLP + tensor-core (tf32 mma) q/k projection ----------------
// Block = 256 threads = 8 warps, 64 edges (E = 6250 * 64 exactly).
// Phase A: warp w computes z (layer 1) for its 8 edges, stages tf32 z in SMEM,
//          computes vsum via exact fp32 butterfly.
// Phase B: block GEMM [64x32] @ [32x256 (q||k)] via mma.sync.m16n8k8.tf32:
//          warp w owns output columns [32w, 32w+32) -> warps 0-3 write q, 4-7 k.
// Prologue: zero g_sn/out + full stage-3 S3 accumulation (independent work).
#define ZSTR 36
#define WSTR 264
__global__ void __launch_bounds__(256) k_edge(
    const float* __restrict__ x, const int* __restrict__ ei,
    const float* __restrict__ ea,
    const float* __restrict__ W1, const float* __restrict__ b1,
    const int* __restrict__ nni,
    float* __restrict__ out, int N, int E, int C)
{
    __shared__ float  W1s[34 * 32];        // 4352 B
    __shared__ float  b1s[32];             //  128 B
    __shared__ unsigned int Ws[32 * WSTR]; // 33792 B  tf32 weights, q||k cols
    __shared__ unsigned int zt[64 * ZSTR]; //  9216 B  tf32 z
    __shared__ float  bqk[256];            // 1024 B
    __shared__ float4 W2vs[32];            //  512 B
    __shared__ float4 bvs;                 //   16 B

    int tid = threadIdx.x;

    // ---- folded zero-init + stage-3 S3 accumulation ----
    {
        int g = blockIdx.x * 256 + tid;
        const float4 z4 = make_float4(0.f, 0.f, 0.f, 0.f);
        if (g < E) {
            ((float4*)g_sn)[2 * g + 0] = z4;
            ((float4*)g_sn)[2 * g + 1] = z4;
        }
        if (g < N) out[g] = 0.f;
        if (g < C) {
            int ns = nni[g], nd = nni[C + g];
            float s = __ldg(x + ns) * __ldg(x + nd);
            float4 ev;
            ev.x = __expf(s * g_whk[0]);
            ev.y = __expf(s * g_whk[1]);
            ev.z = __expf(s * g_whk[2]);
            ev.w = __expf(s * g_whk[3]);
            atomicAdd(&g_S3[nd], ev);
        }
    }

    // ---- SMEM fills ----
    for (int i = tid; i < 34 * 32; i += 256) W1s[i] = W1[i];
    if (tid < 32) b1s[tid] = b1[tid];
    for (int i = tid; i < 8192; i += 256) {
        int k = i >> 8, c = i & 255;
        float v = (c < 128) ? g_W2q[k * 128 + c] : g_W2k[k * 128 + (c - 128)];
        Ws[k * WSTR + c] = f2tf32(v);
    }
    if (tid < 256) bqk[tid] = (tid < 128) ? g_bq[tid] : g_bk[tid - 128];
    if (tid < 32) W2vs[tid] = g_W2v[tid];
    if (tid == 0) bvs = g_bv;
    __syncthreads();

    int lane = tid & 31;
    int warp = tid >> 5;
    int e0w = blockIdx.x * 64 + warp * 8;   // this warp's 8 edges

    // ---- Phase A: layer 1 (z), stage z in SMEM, vsum ----
    float z[8];
    #pragma unroll
    for (int j = 0; j < 8; j++) {
        int e = e0w + j;
        int s = ei[e], d = ei[E + e];
        float xs = __ldg(x + s);
        float xd = __ldg(x + d);
        float eav = __ldg(ea + (size_t)e * 32 + lane);

        float acc = b1s[lane];
        acc = fmaf(xs, W1s[lane], acc);
        acc = fmaf(xd, W1s[32 + lane], acc);
        #pragma unroll
        for (int i = 0; i < 32; i++)
            acc = fmaf(__shfl_sync(FULLMASK, eav, i), W1s[(2 + i) * 32 + lane], acc);
        z[j] = fmaxf(acc, 0.f);
        zt[(warp * 8 + j) * ZSTR + lane] = f2tf32(z[j]);
    }

    // vsum[e] = z @ W2v + bv (exact fp32 butterfly)
    {
        float4 wv = W2vs[lane];
        float4 bv = bvs;
        #pragma unroll
        for (int j = 0; j < 8; j++) {
            float4 t;
            t.x = z[j] * wv.x; t.y = z[j] * wv.y;
            t.z = z[j] * wv.z; t.w = z[j] * wv.w;
            #pragma unroll
            for (int off = 16; off; off >>= 1) {
                t.x += __shfl_xor_sync(FULLMASK, t.x, off);
                t.y += __shfl_xor_sync(FULLMASK, t.y, off);
                t.z += __shfl_xor_sync(FULLMASK, t.z, off);
                t.w += __shfl_xor_sync(FULLMASK, t.w, off);
            }
            if (lane == 0)
                g_vsum[e0w + j] = make_float4(t.x + bv.x, t.y + bv.y,
                                              t.z + bv.z, t.w + bv.w);
        }
    }
    __syncthreads();

    // ---- Phase B: tf32 mma projection. warp owns 32 cols of q||k ----
    {
        int g = lane >> 2, t = lane & 3;
        int wslice = warp * 32;
        __half* base = (warp < 4) ? g_qh : g_kh;
        int cbase = (warp < 4) ? wslice : (wslice - 128);
        int e0blk = blockIdx.x * 64;

        // preload all B fragments (16 n/k tiles x 2 regs)
        unsigned int bf[4][4][2];
        #pragma unroll
        for (int nt = 0; nt < 4; nt++)
            #pragma unroll
            for (int ks = 0; ks < 4; ks++) {
                int k0 = ks * 8 + t;
                int col = wslice + nt * 8 + g;
                bf[nt][ks][0] = Ws[k0 * WSTR + col];
                bf[nt][ks][1] = Ws[(k0 + 4) * WSTR + col];
            }

        #pragma unroll
        for (int mt = 0; mt < 4; mt++) {
            unsigned int af[4][4];
            #pragma unroll
            for (int ks = 0; ks < 4; ks++) {
                int r0 = mt * 16 + g, kk = ks * 8 + t;
                af[ks][0] = zt[r0 * ZSTR + kk];
                af[ks][1] = zt[(r0 + 8) * ZSTR + kk];
                af[ks][2] = zt[r0 * ZSTR + kk + 4];
                af[ks][3] = zt[(r0 + 8) * ZSTR + kk + 4];
            }
            #pragma unroll
            for (int nt = 0; nt < 4; nt++) {
                float c0 = 0.f, c1 = 0.f, c2 = 0.f, c3 = 0.f;
                #pragma unroll
                for (int ks = 0; ks < 4; ks++) {
                    asm volatile(
                        "mma.sync.aligned.m16n8k8.row.col.f32.tf32.tf32.f32 "
                        "{%0,%1,%2,%3}, {%4,%5,%6,%7}, {%8,%9}, {%0,%1,%2,%3};"
                        : "+f"(c0), "+f"(c1), "+f"(c2), "+f"(c3)
                        : "r"(af[ks][0]), "r"(af[ks][1]), "r"(af[ks][2]), "r"(af[ks][3]),
                          "r"(bf[nt][ks][0]), "r"(bf[nt][ks][1]));
                }
                int col = wslice + nt * 8 + 2 * t;
                float2 bia = *(const float2*)(bqk + col);
                c0 += bia.x; c1 += bia.y; c2 += bia.x; c3 += bia.y;
                __half2 h01 = __floats2half2_rn(c0, c1);
                __half2 h23 = __floats2half2_rn(c2, c3);
                int lcol = cbase + nt * 8 + 2 * t;
                int er0 = e0blk + mt * 16 + g;
                *(__half2*)(base + (size_t)er0 * 128 + lcol) = h01;
                *(__half2*)(base + (size_t)(er0 + 8) * 128 + lcol) = h23;
            }
        }
    }
}

// ---------------- K2: fused logits + exp + segment accumulation ----------------
// 4 ee-pairs per warp. fp16 q/k, fp32 dot. Vector float2 atomics.
#define PPW 4
__global__ void __launch_bounds__(256) k_attn(const int* __restrict__ eei, int EE) {
    int warp = (blockIdx.x * 256 + threadIdx.x) >> 5;
    int lane = threadIdx.x & 31;
    int base = warp * PPW;
    if (base >= EE) return;

    int es[PPW], ed[PPW];
    #pragma unroll
    for (int i = 0; i < PPW; i++) {
        int e = base + i; if (e >= EE) e = EE - 1;
        es[i] = __ldg(eei + e);
        ed[i] = __ldg(eei + EE + e);
    }

    uint2 qp[PPW], kp[PPW];
    #pragma unroll
    for (int i = 0; i < PPW; i++) {
        qp[i] = __ldg((const uint2*)g_qh + (size_t)ed[i] * 32 + lane);
        kp[i] = __ldg((const uint2*)g_kh + (size_t)es[i] * 32 + lane);
    }

    #pragma unroll
    for (int i = 0; i < PPW; i++) {
        float2 q0 = __half22float2(*(__half2*)&qp[i].x);
        float2 q1 = __half22float2(*(__half2*)&qp[i].y);
        float2 k0 = __half22float2(*(__half2*)&kp[i].x);
        float2 k1 = __half22float2(*(__half2*)&kp[i].y);
        float p = q0.x * k0.x + q0.y * k0.y + q1.x * k1.x + q1.y * k1.y;
        p += __shfl_xor_sync(FULLMASK, p, 1);
        p += __shfl_xor_sync(FULLMASK, p, 2);
        p += __shfl_xor_sync(FULLMASK, p, 4);
        if ((lane & 7) == 0 && base + i < EE) {
            int h = lane >> 3;
            float ex = __expf(p * 0.17677669529663687f);
            float v = ((const float*)g_vsum)[(size_t)es[i] * 4 + h];
            atomicAdd(&g_sn[(size_t)ed[i] * 4 + h], make_float2(ex, ex * v));
        }
    }
}

// ---------------- K3: uef + stage3 messages (merged final pass) ----------------
__global__ void k_n3(float* __restrict__ out, const float* __restrict__ x,
                     const int* __restrict__ nni, int N, int E, int C) {
    int c = blockIdx.x * blockDim.x + threadIdx.x;
    if (c < E) {
        float4 a = ((const float4*)g_sn)[2 * c + 0];  // (s0,n0,s1,n1)
        float4 b = ((const float4*)g_sn)[2 * c + 1];  // (s2,n2,s3,n3)
        float u = a.y / (a.x + 1e-16f) + a.w / (a.z + 1e-16f)
                + b.y / (b.x + 1e-16f) + b.w / (b.z + 1e-16f);
        out[N + c] = u * (1.f / 128.f);
    }
    if (c < C) {
        int ns = nni[c], nd = nni[C + c];
        float xs = __ldg(x + ns);
        float s = xs * __ldg(x + nd);
        float4 S = g_S3[nd];
        const float* Sf = (const float*)&S;
        float acc = 0.f;
        #pragma unroll
        for (int h = 0; h < 4; h++) {
            float al = __expf(s * g_whk[h]) / (Sf[h] + 1e-16f);
            acc = fmaf(al, g_wv[h], acc);
        }
        atomicAdd(&out[nd], acc * xs * (1.f / 128.f));
    }
}

// ---------------- launch ----------------
extern "C" void kernel_launch(void* const* d_in, const int* in_sizes, int n_in,
                              void* d_out, int out_size) {
    const float* x   = (const float*)d_in[0];
    const int*   ei  = (const int*)d_in[1];
    const float* ea  = (const float*)d_in[2];
    const int*   eei = (const int*)d_in[3];
    const int*   nni = (const int*)d_in[4];
    const float* W1  = (const float*)d_in[5];
    const float* b1  = (const float*)d_in[6];
    const float* W2  = (const float*)d_in[7];
    const float* b2  = (const float*)d_in[8];
    const float* Wq  = (const float*)d_in[9];
    const float* Wk  = (const float*)d_in[10];
    const float* Wv  = (const float*)d_in[11];
    const float* Wq2 = (const float*)d_in[12];
    const float* Wk2 = (const float*)d_in[13];
    const float* Wv2 = (const float*)d_in[14];
    float* out = (float*)d_out;

    int N  = in_sizes[0];
    int E  = in_sizes[1] / 2;
    int EE = in_sizes[3] / 2;
    int C  = in_sizes[4] / 2;

    k_prep_all<<<(8704 + N + 255) / 256, 256>>>(W2, b2, Wq, Wk, Wv, Wq2, Wk2, Wv2, N);
    k_edge<<<(E + 63) / 64, 256>>>(x, ei, ea, W1, b1, nni, out, N, E, C);
    k_attn<<<(EE + 8 * PPW - 1) / (8 * PPW), 256>>>(eei, EE);
    k_n3<<<(C + 255) / 256, 256>>>(out, x, nni, N, E, C);
}

// round 11
// speedup vs baseline: 1.1499x; 1.1499x over previous
#include <cuda_runtime.h>
#include <cuda_fp16.h>
#include <math_constants.h>

// Problem-shape constants (fixed by setup_inputs)
#define NN   50000
#define EN   400000
#define EEN  800000
#define CN   800000

#define FULLMASK 0xffffffffu

// ---------------- static scratch (no allocation allowed) ----------------
__device__ __half  g_qh[(size_t)EN * 128];    // [E,128] q projection (fp16 storage)
__device__ __half  g_kh[(size_t)EN * 128];    // [E,128] k projection (fp16 storage)
__device__ float4 g_vsum[EN];                 // [E,4]  per-head summed v
__device__ float2 g_sn[(size_t)EN * 4];       // [E,4] interleaved (exp-sum, exp*vsum)
__device__ float4 g_S3[NN];                   // stage3 per-head exp-sum
__device__ float  g_whk[4];
__device__ float  g_wv[4];
// tf32 B-fragments for the projection MMA, laid out exactly per-lane:
// index = warp*1024 + nt*256 + ks*64 + r*32 + lane
__device__ unsigned int g_bfrag[8192];
__device__ float  g_bq[128];                  // b2 @ Wq
__device__ float  g_bk[128];                  // b2 @ Wk
__device__ float4 g_W2v[32];                  // W2 @ wvh  [32,4]
__device__ float4 g_bv;                       // b2 @ wvh

__device__ __forceinline__ unsigned int f2tf32(float f) {
    unsigned int r;
    asm("cvt.rna.tf32.f32 %0, %1;" : "=r"(r) : "f"(f));
    return r;
}

// ---------------- K_prep_all: weight folding + MMA fragment layout + S3 zero ----------------
__global__ void k_prep_all(const float* __restrict__ W2, const float* __restrict__ b2,
                           const float* __restrict__ Wq, const float* __restrict__ Wk,
                           const float* __restrict__ Wv,
                           const float* __restrict__ Wq2,
                           const float* __restrict__ Wk2,
                           const float* __restrict__ Wv2, int N) {
    int idx = blockIdx.x * 256 + threadIdx.x;
    if (idx < 8192) {                       // B fragments, lane-exact layout
        int lane = idx & 31;
        int r  = (idx >> 5) & 1;
        int ks = (idx >> 6) & 3;
        int nt = (idx >> 8) & 3;
        int w  = idx >> 10;
        int col = w * 32 + nt * 8 + (lane >> 2);   // 0..255 (q||k)
        int kk  = ks * 8 + (lane & 3) + r * 4;     // 0..31
        const float* Wx = (col < 128) ? Wq : Wk;
        int c = (col < 128) ? col : (col - 128);
        float s = 0.f;
        for (int m = 0; m < 128; m++) s += W2[kk * 128 + m] * Wx[m * 128 + c];
        g_bfrag[idx] = f2tf32(s);
    } else if (idx < 8320) {                // bq
        int c = idx - 8192;
        float s = 0.f;
        for (int m = 0; m < 128; m++) s += b2[m] * Wq[m * 128 + c];
        g_bq[c] = s;
    } else if (idx < 8448) {                // bk
        int c = idx - 8320;
        float s = 0.f;
        for (int m = 0; m < 128; m++) s += b2[m] * Wk[m * 128 + c];
        g_bk[c] = s;
    } else if (idx < 8576) {                // W2v [32][4] (wvh recomputed inline)
        int i = idx - 8448;
        int r = i >> 2, hh = i & 3;
        float s = 0.f;
        for (int m = 0; m < 128; m++) {
            float w = 0.f;
            for (int d = 0; d < 32; d++) w += Wv[m * 128 + hh * 32 + d];
            s += W2[r * 128 + m] * w;
        }
        ((float*)&g_W2v[r])[hh] = s;
    } else if (idx < 8580) {                // bv
        int hh = idx - 8576;
        float s = 0.f;
        for (int m = 0; m < 128; m++) {
            float w = 0.f;
            for (int d = 0; d < 32; d++) w += Wv[m * 128 + hh * 32 + d];
            s += b2[m] * w;
        }
        ((float*)&g_bv)[hh] = s;
    } else if (idx < 8584) {                // whk
        int h = idx - 8580;
        float qk = 0.f;
        for (int d = 0; d < 32; d++) qk += Wq2[h * 32 + d] * Wk2[h * 32 + d];
        g_whk[h] = qk * 0.17677669529663687f;   // 1/sqrt(32)
    } else if (idx < 8588) {                // wv
        int h = idx - 8584;
        float vv = 0.f;
        for (int d = 0; d < 32; d++) vv += Wv2[h * 32 + d];
        g_wv[h] = vv;
    } else {                                // zero g_S3 (consumed by k_edge atomics)
        int j = idx - 8704;
        if (j >= 0 && j < N)
            g_S3[j] = make_float4(0.f, 0.f, 0.f, 0.f);
    }
}

// ---------------- K1: edge MLP + tensor-core (tf32 mma) q/k projection ----------------
// Block = 256 threads = 8 warps, 64 edges (E = 6250 * 64 exactly).
// Phase A: warp w computes z (layer 1) for its 8 edges, stages tf32 z in SMEM,
//          computes vsum via exact fp32 butterfly.
// Phase B: block GEMM [64x32] @ [32x256 (q||k)] via mma.sync.m16n8k8.tf32.
//          B fragments come pre-laid-out from g_bfrag (32 coalesced LDG, L2-hot).
// Prologue: zero g_sn/out + full stage-3 S3 accumulation (independent work).
#define ZSTR 36
__global__ void __launch_bounds__(256) k_edge(
    const float* __restrict__ x, const int* __restrict__ ei,
    const float* __restrict__ ea,
    const float* __restrict__ W1, const float* __restrict__ b1,
    const int* __restrict__ nni,
    float* __restrict__ out, int N, int E, int C)
{
    __shared__ float  W1s[34 * 32];        // 4352 B
    __shared__ float  b1s[32];             //  128 B
    __shared__ unsigned int zt[64 * ZSTR]; //  9216 B  tf32 z
    __shared__ float  bqk[256];            // 1024 B
    __shared__ float4 W2vs[32];            //  512 B
    __shared__ float4 bvs;                 //   16 B

    int tid = threadIdx.x;

    // ---- folded zero-init + stage-3 S3 accumulation ----
    {
        int g = blockIdx.x * 256 + tid;
        const float4 z4 = make_float4(0.f, 0.f, 0.f, 0.f);
        if (g < E) {
            ((float4*)g_sn)[2 * g + 0] = z4;
            ((float4*)g_sn)[2 * g + 1] = z4;
        }
        if (g < N) out[g] = 0.f;
        if (g < C) {
            int ns = nni[g], nd = nni[C + g];
            float s = __ldg(x + ns) * __ldg(x + nd);
            float4 ev;
            ev.x = __expf(s * g_whk[0]);
            ev.y = __expf(s * g_whk[1]);
            ev.z = __expf(s * g_whk[2]);
            ev.w = __expf(s * g_whk[3]);
            atomicAdd(&g_S3[nd], ev);
        }
    }

    // ---- SMEM fills (small) ----
    for (int i = tid; i < 34 * 32; i += 256) W1s[i] = W1[i];
    if (tid < 32) b1s[tid] = b1[tid];
    bqk[tid] = (tid < 128) ? g_bq[tid] : g_bk[tid - 128];
    if (tid < 32) W2vs[tid] = g_W2v[tid];
    if (tid == 0) bvs = g_bv;

    int lane = tid & 31;
    int warp = tid >> 5;
    int e0w = blockIdx.x * 64 + warp * 8;   // this warp's 8 edges

    // ---- preload B fragments (L2-hot table, coalesced) ----
    unsigned int bf[4][4][2];
    #pragma unroll
    for (int nt = 0; nt < 4; nt++)
        #pragma unroll
        for (int ks = 0; ks < 4; ks++)
            #pragma unroll
            for (int r = 0; r < 2; r++)
                bf[nt][ks][r] = __ldg(g_bfrag + warp * 1024 + nt * 256 + ks * 64 + r * 32 + lane);

    __syncthreads();   // W1s/b1s ready

    // ---- Phase A: layer 1 (z), stage z in SMEM, vsum ----
    float z[8];
    #pragma unroll
    for (int j = 0; j < 8; j++) {
        int e = e0w + j;
        int s = ei[e], d = ei[E + e];
        float xs = __ldg(x + s);
        float xd = __ldg(x + d);
        float eav = __ldg(ea + (size_t)e * 32 + lane);

        float acc = b1s[lane];
        acc = fmaf(xs, W1s[lane], acc);
        acc = fmaf(xd, W1s[32 + lane], acc);
        #pragma unroll
        for (int i = 0; i < 32; i++)
            acc = fmaf(__shfl_sync(FULLMASK, eav, i), W1s[(2 + i) * 32 + lane], acc);
        z[j] = fmaxf(acc, 0.f);
        zt[(warp * 8 + j) * ZSTR + lane] = f2tf32(z[j]);
    }

    // vsum[e] = z @ W2v + bv (exact fp32 butterfly)
    {
        float4 wv = W2vs[lane];
        float4 bv = bvs;
        #pragma unroll
        for (int j = 0; j < 8; j++) {
            float4 t;
            t.x = z[j] * wv.x; t.y = z[j] * wv.y;
            t.z = z[j] * wv.z; t.w = z[j] * wv.w;
            #pragma unroll
            for (int off = 16; off; off >>= 1) {
                t.x += __shfl_xor_sync(FULLMASK, t.x, off);
                t.y += __shfl_xor_sync(FULLMASK, t.y, off);
                t.z += __shfl_xor_sync(FULLMASK, t.z, off);
                t.w += __shfl_xor_sync(FULLMASK, t.w, off);
            }
            if (lane == 0)
                g_vsum[e0w + j] = make_float4(t.x + bv.x, t.y + bv.y,
                                              t.z + bv.z, t.w + bv.w);
        }
    }
    __syncthreads();   // all zt written

    // ---- Phase B: tf32 mma projection. warp owns 32 cols of q||k ----
    {
        int g = lane >> 2, t = lane & 3;
        int wslice = warp * 32;
        __half* base = (warp < 4) ? g_qh : g_kh;
        int cbase = (warp < 4) ? wslice : (wslice - 128);
        int e0blk = blockIdx.x * 64;

        #pragma unroll
        for (int mt = 0; mt < 4; mt++) {
            unsigned int af[4][4];
            #pragma unroll
            for (int ks = 0; ks < 4; ks++) {
                int r0 = mt * 16 + g, kk = ks * 8 + t;
                af[ks][0] = zt[r0 * ZSTR + kk];
                af[ks][1] = zt[(r0 + 8) * ZSTR + kk];
                af[ks][2] = zt[r0 * ZSTR + kk + 4];
                af[ks][3] = zt[(r0 + 8) * ZSTR + kk + 4];
            }
            #pragma unroll
            for (int nt = 0; nt < 4; nt++) {
                float c0 = 0.f, c1 = 0.f, c2 = 0.f, c3 = 0.f;
                #pragma unroll
                for (int ks = 0; ks < 4; ks++) {
                    asm volatile(
                        "mma.sync.aligned.m16n8k8.row.col.f32.tf32.tf32.f32 "
                        "{%0,%1,%2,%3}, {%4,%5,%6,%7}, {%8,%9}, {%0,%1,%2,%3};"
                        : "+f"(c0), "+f"(c1), "+f"(c2), "+f"(c3)
                        : "r"(af[ks][0]), "r"(af[ks][1]), "r"(af[ks][2]), "r"(af[ks][3]),
                          "r"(bf[nt][ks][0]), "r"(bf[nt][ks][1]));
                }
                int col = wslice + nt * 8 + 2 * t;
                float2 bia = *(const float2*)(bqk + col);
                c0 += bia.x; c1 += bia.y; c2 += bia.x; c3 += bia.y;
                __half2 h01 = __floats2half2_rn(c0, c1);
                __half2 h23 = __floats2half2_rn(c2, c3);
                int lcol = cbase + nt * 8 + 2 * t;
                int er0 = e0blk + mt * 16 + g;
                *(__half2*)(base + (size_t)er0 * 128 + lcol) = h01;
                *(__half2*)(base + (size_t)(er0 + 8) * 128 + lcol) = h23;
            }
        }
    }
}

// ---------------- K2: fused logits + exp + segment accumulation ----------------
// 4 ee-pairs per warp. fp16 q/k, fp32 dot. Vector float2 atomics.
#define PPW 4
__global__ void __launch_bounds__(256) k_attn(const int* __restrict__ eei, int EE) {
    int warp = (blockIdx.x * 256 + threadIdx.x) >> 5;
    int lane = threadIdx.x & 31;
    int base = warp * PPW;
    if (base >= EE) return;

    int es[PPW], ed[PPW];
    #pragma unroll
    for (int i = 0; i < PPW; i++) {
        int e = base + i; if (e >= EE) e = EE - 1;
        es[i] = __ldg(eei + e);
        ed[i] = __ldg(eei + EE + e);
    }

    uint2 qp[PPW], kp[PPW];
    #pragma unroll
    for (int i = 0; i < PPW; i++) {
        qp[i] = __ldg((const uint2*)g_qh + (size_t)ed[i] * 32 + lane);
        kp[i] = __ldg((const uint2*)g_kh + (size_t)es[i] * 32 + lane);
    }

    #pragma unroll
    for (int i = 0; i < PPW; i++) {
        float2 q0 = __half22float2(*(__half2*)&qp[i].x);
        float2 q1 = __half22float2(*(__half2*)&qp[i].y);
        float2 k0 = __half22float2(*(__half2*)&kp[i].x);
        float2 k1 = __half22float2(*(__half2*)&kp[i].y);
        float p = q0.x * k0.x + q0.y * k0.y + q1.x * k1.x + q1.y * k1.y;
        p += __shfl_xor_sync(FULLMASK, p, 1);
        p += __shfl_xor_sync(FULLMASK, p, 2);
        p += __shfl_xor_sync(FULLMASK, p, 4);
        if ((lane & 7) == 0 && base + i < EE) {
            int h = lane >> 3;
            float ex = __expf(p * 0.17677669529663687f);
            float v = ((const float*)g_vsum)[(size_t)es[i] * 4 + h];
            atomicAdd(&g_sn[(size_t)ed[i] * 4 + h], make_float2(ex, ex * v));
        }
    }
}

// ---------------- K3: uef + stage3 messages (merged final pass) ----------------
__global__ void k_n3(float* __restrict__ out, const float* __restrict__ x,
                     const int* __restrict__ nni, int N, int E, int C) {
    int c = blockIdx.x * blockDim.x + threadIdx.x;
    if (c < E) {
        float4 a = ((const float4*)g_sn)[2 * c + 0];  // (s0,n0,s1,n1)
        float4 b = ((const float4*)g_sn)[2 * c + 1];  // (s2,n2,s3,n3)
        float u = a.y / (a.x + 1e-16f) + a.w / (a.z + 1e-16f)
                + b.y / (b.x + 1e-16f) + b.w / (b.z + 1e-16f);
        out[N + c] = u * (1.f / 128.f);
    }
    if (c < C) {
        int ns = nni[c], nd = nni[C + c];
        float xs = __ldg(x + ns);
        float s = xs * __ldg(x + nd);
        float4 S = g_S3[nd];
        const float* Sf = (const float*)&S;
        float acc = 0.f;
        #pragma unroll
        for (int h = 0; h < 4; h++) {
            float al = __expf(s * g_whk[h]) / (Sf[h] + 1e-16f);
            acc = fmaf(al, g_wv[h], acc);
        }
        atomicAdd(&out[nd], acc * xs * (1.f / 128.f));
    }
}

// ---------------- launch ----------------
extern "C" void kernel_launch(void* const* d_in, const int* in_sizes, int n_in,
                              void* d_out, int out_size) {
    const float* x   = (const float*)d_in[0];
    const int*   ei  = (const int*)d_in[1];
    const float* ea  = (const float*)d_in[2];
    const int*   eei = (const int*)d_in[3];
    const int*   nni = (const int*)d_in[4];
    const float* W1  = (const float*)d_in[5];
    const float* b1  = (const float*)d_in[6];
    const float* W2  = (const float*)d_in[7];
    const float* b2  = (const float*)d_in[8];
    const float* Wq  = (const float*)d_in[9];
    const float* Wk  = (const float*)d_in[10];
    const float* Wv  = (const float*)d_in[11];
    const float* Wq2 = (const float*)d_in[12];
    const float* Wk2 = (const float*)d_in[13];
    const float* Wv2 = (const float*)d_in[14];
    float* out = (float*)d_out;

    int N  = in_sizes[0];
    int E  = in_sizes[1] / 2;
    int EE = in_sizes[3] / 2;
    int C  = in_sizes[4] / 2;

    k_prep_all<<<(8704 + N + 255) / 256, 256>>>(W2, b2, Wq, Wk, Wv, Wq2, Wk2, Wv2, N);
    k_edge<<<(E + 63) / 64, 256>>>(x, ei, ea, W1, b1, nni, out, N, E, C);
    k_attn<<<(EE + 8 * PPW - 1) / (8 * PPW), 256>>>(eei, EE);
    k_n3<<<(C + 255) / 256, 256>>>(out, x, nni, N, E, C);
}

// round 12
// speedup vs baseline: 1.4488x; 1.2600x over previous
#include <cuda_runtime.h>
#include <cuda_fp16.h>
#include <math_constants.h>

// Problem-shape constants (fixed by setup_inputs)
#define NN   50000
#define EN   400000
#define EEN  800000
#define CN   800000

#define FULLMASK 0xffffffffu

// ---------------- static scratch (no allocation allowed) ----------------
__device__ __half  g_qh[(size_t)EN * 128];    // [E,128] q projection (fp16 storage)
__device__ __half  g_kh[(size_t)EN * 128];    // [E,128] k projection (fp16 storage)
__device__ float4 g_vsum[EN];                 // [E,4]  per-head summed v
__device__ float2 g_sn[(size_t)EN * 4];       // [E,4] interleaved (exp-sum, exp*vsum)
__device__ float4 g_S3[NN];                   // stage3 per-head exp-sum
__device__ float  g_whk[4];
__device__ float  g_wv[4];
// tf32 B-fragments for the projection MMA, laid out exactly per-lane:
// index = warp*1024 + nt*256 + ks*64 + r*32 + lane
__device__ unsigned int g_bfrag[8192];
__device__ float  g_bq[128];                  // b2 @ Wq
__device__ float  g_bk[128];                  // b2 @ Wk
__device__ float4 g_W2v[32];                  // W2 @ wvh  [32,4]
__device__ float4 g_bv;                       // b2 @ wvh

__device__ __forceinline__ unsigned int f2tf32(float f) {
    unsigned int r;
    asm("cvt.rna.tf32.f32 %0, %1;" : "=r"(r) : "f"(f));
    return r;
}
__device__ __forceinline__ unsigned long long pk2(float a, float b) {
    unsigned long long r;
    asm("mov.b64 %0, {%1, %2};" : "=l"(r) : "f"(a), "f"(b));
    return r;
}
__device__ __forceinline__ void ffma2(unsigned long long& d,
                                      unsigned long long a,
                                      unsigned long long b) {
    asm("fma.rn.f32x2 %0, %1, %2, %0;" : "+l"(d) : "l"(a), "l"(b));
}
__device__ __forceinline__ float2 unpk(unsigned long long v) {
    float2 r;
    asm("mov.b64 {%0, %1}, %2;" : "=f"(r.x), "=f"(r.y) : "l"(v));
    return r;
}

// ---------------- K_prep_all: weight folding + MMA fragment layout + S3 zero ----------------
__global__ void k_prep_all(const float* __restrict__ W2, const float* __restrict__ b2,
                           const float* __restrict__ Wq, const float* __restrict__ Wk,
                           const float* __restrict__ Wv,
                           const float* __restrict__ Wq2,
                           const float* __restrict__ Wk2,
                           const float* __restrict__ Wv2, int N) {
    int idx = blockIdx.x * 256 + threadIdx.x;
    if (idx < 8192) {                       // B fragments, lane-exact layout
        int lane = idx & 31;
        int r  = (idx >> 5) & 1;
        int ks = (idx >> 6) & 3;
        int nt = (idx >> 8) & 3;
        int w  = idx >> 10;
        int col = w * 32 + nt * 8 + (lane >> 2);   // 0..255 (q||k)
        int kk  = ks * 8 + (lane & 3) + r * 4;     // 0..31
        const float* Wx = (col < 128) ? Wq : Wk;
        int c = (col < 128) ? col : (col - 128);
        float s = 0.f;
        for (int m = 0; m < 128; m++) s += W2[kk * 128 + m] * Wx[m * 128 + c];
        g_bfrag[idx] = f2tf32(s);
    } else if (idx < 8320) {                // bq
        int c = idx - 8192;
        float s = 0.f;
        for (int m = 0; m < 128; m++) s += b2[m] * Wq[m * 128 + c];
        g_bq[c] = s;
    } else if (idx < 8448) {                // bk
        int c = idx - 8320;
        float s = 0.f;
        for (int m = 0; m < 128; m++) s += b2[m] * Wk[m * 128 + c];
        g_bk[c] = s;
    } else if (idx < 8576) {                // W2v [32][4] (wvh recomputed inline)
        int i = idx - 8448;
        int r = i >> 2, hh = i & 3;
        float s = 0.f;
        for (int m = 0; m < 128; m++) {
            float w = 0.f;
            for (int d = 0; d < 32; d++) w += Wv[m * 128 + hh * 32 + d];
            s += W2[r * 128 + m] * w;
        }
        ((float*)&g_W2v[r])[hh] = s;
    } else if (idx < 8580) {                // bv
        int hh = idx - 8576;
        float s = 0.f;
        for (int m = 0; m < 128; m++) {
            float w = 0.f;
            for (int d = 0; d < 32; d++) w += Wv[m * 128 + hh * 32 + d];
            s += b2[m] * w;
        }
        ((float*)&g_bv)[hh] = s;
    } else if (idx < 8584) {                // whk
        int h = idx - 8580;
        float qk = 0.f;
        for (int d = 0; d < 32; d++) qk += Wq2[h * 32 + d] * Wk2[h * 32 + d];
        g_whk[h] = qk * 0.17677669529663687f;   // 1/sqrt(32)
    } else if (idx < 8588) {                // wv
        int h = idx - 8584;
        float vv = 0.f;
        for (int d = 0; d < 32; d++) vv += Wv2[h * 32 + d];
        g_wv[h] = vv;
    } else {                                // zero g_S3 (consumed by k_edge atomics)
        int j = idx - 8704;
        if (j >= 0 && j < N)
            g_S3[j] = make_float4(0.f, 0.f, 0.f, 0.f);
    }
}

// ---------------- K1: edge MLP + tensor-core (tf32 mma) q/k projection ----------------
// Block = 256 threads = 8 warps, 64 edges (E = 6250 * 64 exactly).
// Phase A: layer-1 z in exact fp32 via transposed-ea SMEM + packed FFMA2
//          (edge pairs), vsum via SMEM per-lane dot (lane = edge x head).
// Phase B: block GEMM [64x32] @ [32x256 (q||k)] via mma.sync.m16n8k8.tf32;
//          B fragments pre-laid in g_bfrag (loaded after Phase A: low regs).
// Prologue: zero g_sn/out + full stage-3 S3 accumulation (independent work).
#define ZSTR 36
#define EASTR 10
#define ZSSTR 33
__global__ void __launch_bounds__(256) k_edge(
    const float* __restrict__ x, const int* __restrict__ ei,
    const float* __restrict__ ea,
    const float* __restrict__ W1, const float* __restrict__ b1,
    const int* __restrict__ nni,
    float* __restrict__ out, int N, int E, int C)
{
    __shared__ float  W1s[34 * 32];            // 4352 B
    __shared__ float  b1s[32];                 //  128 B
    __shared__ unsigned int zt[64 * ZSTR];     // 9216 B  tf32 z (for MMA A frags)
    __shared__ float  zs[8 * 8 * ZSSTR];       // 8448 B  fp32 z (for vsum dots)
    __shared__ float  eat[8 * 32 * EASTR];     // 10240 B transposed ea per warp
    __shared__ float  bqk[256];                // 1024 B
    __shared__ float4 W2vs[32];                //  512 B
    __shared__ float4 bvs;                     //   16 B

    int tid = threadIdx.x;

    // ---- folded zero-init + stage-3 S3 accumulation ----
    {
        int g = blockIdx.x * 256 + tid;
        const float4 z4 = make_float4(0.f, 0.f, 0.f, 0.f);
        if (g < E) {
            ((float4*)g_sn)[2 * g + 0] = z4;
            ((float4*)g_sn)[2 * g + 1] = z4;
        }
        if (g < N) out[g] = 0.f;
        if (g < C) {
            int ns = nni[g], nd = nni[C + g];
            float s = __ldg(x + ns) * __ldg(x + nd);
            float4 ev;
            ev.x = __expf(s * g_whk[0]);
            ev.y = __expf(s * g_whk[1]);
            ev.z = __expf(s * g_whk[2]);
            ev.w = __expf(s * g_whk[3]);
            atomicAdd(&g_S3[nd], ev);
        }
    }

    // ---- SMEM fills (small) ----
    for (int i = tid; i < 34 * 32; i += 256) W1s[i] = W1[i];
    if (tid < 32) b1s[tid] = b1[tid];
    bqk[tid] = (tid < 128) ? g_bq[tid] : g_bk[tid - 128];
    if (tid < 32) W2vs[tid] = g_W2v[tid];
    if (tid == 0) bvs = g_bv;

    int lane = tid & 31;
    int warp = tid >> 5;
    int e0w = blockIdx.x * 64 + warp * 8;   // this warp's 8 edges

    // ---- gather endpoint x values: lanes 0-7 -> xs, lanes 8-15 -> xd ----
    float xv = 0.f;
    if (lane < 16) {
        int e = e0w + (lane & 7);
        int idx = (lane < 8) ? ei[e] : ei[E + e];
        xv = __ldg(x + idx);
    }

    // ---- stage ea transposed: eat[m][edge] (per-warp tile) ----
    {
        float* eatw = eat + warp * 32 * EASTR;
        const float4* ea4 = (const float4*)(ea + (size_t)e0w * 32);
        #pragma unroll
        for (int r = 0; r < 2; r++) {
            float4 v = __ldg(ea4 + r * 32 + lane);
            int j  = r * 4 + (lane >> 3);
            int m0 = (lane & 7) * 4;
            eatw[(m0 + 0) * EASTR + j] = v.x;
            eatw[(m0 + 1) * EASTR + j] = v.y;
            eatw[(m0 + 2) * EASTR + j] = v.z;
            eatw[(m0 + 3) * EASTR + j] = v.w;
        }
    }
    __syncthreads();   // W1s/b1s + eat visible

    // ---- Phase A: layer 1, packed over edge pairs (exact fp32 per lane) ----
    {
        float bb = b1s[lane];
        unsigned long long wr0 = pk2(W1s[lane], W1s[lane]);
        unsigned long long wr1 = pk2(W1s[32 + lane], W1s[32 + lane]);
        unsigned long long acc2[4];
        #pragma unroll
        for (int p = 0; p < 4; p++) {
            float xs0 = __shfl_sync(FULLMASK, xv, 2 * p);
            float xs1 = __shfl_sync(FULLMASK, xv, 2 * p + 1);
            float xd0 = __shfl_sync(FULLMASK, xv, 8 + 2 * p);
            float xd1 = __shfl_sync(FULLMASK, xv, 9 + 2 * p);
            acc2[p] = pk2(bb, bb);
            ffma2(acc2[p], wr0, pk2(xs0, xs1));
            ffma2(acc2[p], wr1, pk2(xd0, xd1));
        }
        const float* eatw = eat + warp * 32 * EASTR;
        #pragma unroll 8
        for (int m = 0; m < 32; m++) {
            float w = W1s[(2 + m) * 32 + lane];
            unsigned long long wp = pk2(w, w);
            const float* row = eatw + m * EASTR;
            #pragma unroll
            for (int p = 0; p < 4; p++) {
                float2 ep = *(const float2*)(row + 2 * p);
                ffma2(acc2[p], wp, pk2(ep.x, ep.y));
            }
        }
        // relu + stage fp32 (zs) and tf32 (zt)
        float* zsw = zs + warp * 8 * ZSSTR;
        unsigned int* ztw = zt + warp * 8 * ZSTR;
        #pragma unroll
        for (int p = 0; p < 4; p++) {
            float2 zz = unpk(acc2[p]);
            float z0 = fmaxf(zz.x, 0.f);
            float z1 = fmaxf(zz.y, 0.f);
            zsw[(2 * p) * ZSSTR + lane] = z0;
            zsw[(2 * p + 1) * ZSSTR + lane] = z1;
            ztw[(2 * p) * ZSTR + lane] = f2tf32(z0);
            ztw[(2 * p + 1) * ZSTR + lane] = f2tf32(z1);
        }
    }
    __syncwarp();

    // ---- vsum: lane = (edge e = lane>>2, head h = lane&3), serial fp32 dot ----
    {
        int e = lane >> 2, h = lane & 3;
        const float* zsw = zs + warp * 8 * ZSSTR + e * ZSSTR;
        const float* wv = (const float*)W2vs;
        float acc = ((const float*)&bvs)[h];
        #pragma unroll 8
        for (int m = 0; m < 32; m++)
            acc = fmaf(zsw[m], wv[m * 4 + h], acc);
        ((float*)g_vsum)[(size_t)(e0w + e) * 4 + h] = acc;
    }

    // ---- preload B fragments (after Phase A: keeps Phase-A regs low) ----
    unsigned int bf[4][4][2];
    #pragma unroll
    for (int nt = 0; nt < 4; nt++)
        #pragma unroll
        for (int ks = 0; ks < 4; ks++)
            #pragma unroll
            for (int r = 0; r < 2; r++)
                bf[nt][ks][r] = __ldg(g_bfrag + warp * 1024 + nt * 256 + ks * 64 + r * 32 + lane);

    __syncthreads();   // all zt written

    // ---- Phase B: tf32 mma projection. warp owns 32 cols of q||k ----
    {
        int g = lane >> 2, t = lane & 3;
        int wslice = warp * 32;
        __half* base = (warp < 4) ? g_qh : g_kh;
        int cbase = (warp < 4) ? wslice : (wslice - 128);
        int e0blk = blockIdx.x * 64;

        #pragma unroll
        for (int mt = 0; mt < 4; mt++) {
            unsigned int af[4][4];
            #pragma unroll
            for (int ks = 0; ks < 4; ks++) {
                int r0 = mt * 16 + g, kk = ks * 8 + t;
                af[ks][0] = zt[r0 * ZSTR + kk];
                af[ks][1] = zt[(r0 + 8) * ZSTR + kk];
                af[ks][2] = zt[r0 * ZSTR + kk + 4];
                af[ks][3] = zt[(r0 + 8) * ZSTR + kk + 4];
            }
            #pragma unroll
            for (int nt = 0; nt < 4; nt++) {
                float c0 = 0.f, c1 = 0.f, c2 = 0.f, c3 = 0.f;
                #pragma unroll
                for (int ks = 0; ks < 4; ks++) {
                    asm volatile(
                        "mma.sync.aligned.m16n8k8.row.col.f32.tf32.tf32.f32 "
                        "{%0,%1,%2,%3}, {%4,%5,%6,%7}, {%8,%9}, {%0,%1,%2,%3};"
                        : "+f"(c0), "+f"(c1), "+f"(c2), "+f"(c3)
                        : "r"(af[ks][0]), "r"(af[ks][1]), "r"(af[ks][2]), "r"(af[ks][3]),
                          "r"(bf[nt][ks][0]), "r"(bf[nt][ks][1]));
                }
                int col = wslice + nt * 8 + 2 * t;
                float2 bia = *(const float2*)(bqk + col);
                c0 += bia.x; c1 += bia.y; c2 += bia.x; c3 += bia.y;
                __half2 h01 = __floats2half2_rn(c0, c1);
                __half2 h23 = __floats2half2_rn(c2, c3);
                int lcol = cbase + nt * 8 + 2 * t;
                int er0 = e0blk + mt * 16 + g;
                *(__half2*)(base + (size_t)er0 * 128 + lcol) = h01;
                *(__half2*)(base + (size_t)(er0 + 8) * 128 + lcol) = h23;
            }
        }
    }
}

// ---------------- K2: fused logits + exp + segment accumulation ----------------
// 4 ee-pairs per warp. fp16 q/k, fp32 dot. Vector float2 atomics.
#define PPW 4
__global__ void __launch_bounds__(256) k_attn(const int* __restrict__ eei, int EE) {
    int warp = (blockIdx.x * 256 + threadIdx.x) >> 5;
    int lane = threadIdx.x & 31;
    int base = warp * PPW;
    if (base >= EE) return;

    int es[PPW], ed[PPW];
    #pragma unroll
    for (int i = 0; i < PPW; i++) {
        int e = base + i; if (e >= EE) e = EE - 1;
        es[i] = __ldg(eei + e);
        ed[i] = __ldg(eei + EE + e);
    }

    uint2 qp[PPW], kp[PPW];
    #pragma unroll
    for (int i = 0; i < PPW; i++) {
        qp[i] = __ldg((const uint2*)g_qh + (size_t)ed[i] * 32 + lane);
        kp[i] = __ldg((const uint2*)g_kh + (size_t)es[i] * 32 + lane);
    }

    #pragma unroll
    for (int i = 0; i < PPW; i++) {
        float2 q0 = __half22float2(*(__half2*)&qp[i].x);
        float2 q1 = __half22float2(*(__half2*)&qp[i].y);
        float2 k0 = __half22float2(*(__half2*)&kp[i].x);
        float2 k1 = __half22float2(*(__half2*)&kp[i].y);
        float p = q0.x * k0.x + q0.y * k0.y + q1.x * k1.x + q1.y * k1.y;
        p += __shfl_xor_sync(FULLMASK, p, 1);
        p += __shfl_xor_sync(FULLMASK, p, 2);
        p += __shfl_xor_sync(FULLMASK, p, 4);
        if ((lane & 7) == 0 && base + i < EE) {
            int h = lane >> 3;
            float ex = __expf(p * 0.17677669529663687f);
            float v = ((const float*)g_vsum)[(size_t)es[i] * 4 + h];
            atomicAdd(&g_sn[(size_t)ed[i] * 4 + h], make_float2(ex, ex * v));
        }
    }
}

// ---------------- K3: uef + stage3 messages (merged final pass) ----------------
__global__ void k_n3(float* __restrict__ out, const float* __restrict__ x,
                     const int* __restrict__ nni, int N, int E, int C) {
    int c = blockIdx.x * blockDim.x + threadIdx.x;
    if (c < E) {
        float4 a = ((const float4*)g_sn)[2 * c + 0];  // (s0,n0,s1,n1)
        float4 b = ((const float4*)g_sn)[2 * c + 1];  // (s2,n2,s3,n3)
        float u = a.y / (a.x + 1e-16f) + a.w / (a.z + 1e-16f)
                + b.y / (b.x + 1e-16f) + b.w / (b.z + 1e-16f);
        out[N + c] = u * (1.f / 128.f);
    }
    if (c < C) {
        int ns = nni[c], nd = nni[C + c];
        float xs = __ldg(x + ns);
        float s = xs * __ldg(x + nd);
        float4 S = g_S3[nd];
        const float* Sf = (const float*)&S;
        float acc = 0.f;
        #pragma unroll
        for (int h = 0; h < 4; h++) {
            float al = __expf(s * g_whk[h]) / (Sf[h] + 1e-16f);
            acc = fmaf(al, g_wv[h], acc);
        }
        atomicAdd(&out[nd], acc * xs * (1.f / 128.f));
    }
}

// ---------------- launch ----------------
extern "C" void kernel_launch(void* const* d_in, const int* in_sizes, int n_in,
                              void* d_out, int out_size) {
    const float* x   = (const float*)d_in[0];
    const int*   ei  = (const int*)d_in[1];
    const float* ea  = (const float*)d_in[2];
    const int*   eei = (const int*)d_in[3];
    const int*   nni = (const int*)d_in[4];
    const float* W1  = (const float*)d_in[5];
    const float* b1  = (const float*)d_in[6];
    const float* W2  = (const float*)d_in[7];
    const float* b2  = (const float*)d_in[8];
    const float* Wq  = (const float*)d_in[9];
    const float* Wk  = (const float*)d_in[10];
    const float* Wv  = (const float*)d_in[11];
    const float* Wq2 = (const float*)d_in[12];
    const float* Wk2 = (const float*)d_in[13];
    const float* Wv2 = (const float*)d_in[14];
    float* out = (float*)d_out;

    int N  = in_sizes[0];
    int E  = in_sizes[1] / 2;
    int EE = in_sizes[3] / 2;
    int C  = in_sizes[4] / 2;

    k_prep_all<<<(8704 + N + 255) / 256, 256>>>(W2, b2, Wq, Wk, Wv, Wq2, Wk2, Wv2, N);
    k_edge<<<(E + 63) / 64, 256>>>(x, ei, ea, W1, b1, nni, out, N, E, C);
    k_attn<<<(EE + 8 * PPW - 1) / (8 * PPW), 256>>>(eei, EE);
    k_n3<<<(C + 255) / 256, 256>>>(out, x, nni, N, E, C);
}